// round 2
// baseline (speedup 1.0000x reference)
#include <cuda_runtime.h>
#include <stdint.h>

// ---------------------------------------------------------------------------
// Raindrop ObservationPropagation, use_beta=False, heads=1.
//
// Identity: message uses x[tgt] (constant within each softmax segment) and the
// segment softmax gamma sums to exactly 1, so
//   out[n] = relu(x[n] @ Wv + bv) * has_incoming_edge[n]
// edge_weights cancel entirely. Work = edge-target mask scatter + masked
// 50000x96x96 GEMM with bias+relu epilogue.
// ---------------------------------------------------------------------------

#define DIM 96
#define ROWS_PER_BLOCK 32
#define MAX_NODES (1 << 18)   // scratch via __device__ global (no allocs allowed)

__device__ unsigned char g_mask[MAX_NODES];
__device__ int g_is64;

// Zero the node mask; assume int64 edge_index until proven otherwise.
__global__ void rd_init_kernel(int n) {
    int i = blockIdx.x * blockDim.x + threadIdx.x;
    if (i < n) g_mask[i] = 0;
    if (i == 0 && blockIdx.x == 0) g_is64 = 1;
}

// Detect edge_index width. Sample first E/2 64-bit words (source row — region
// in-bounds under both interpretations): int64 -> values in [0,n); int32 ->
// two packed 32-bit indices per word, value >= 2^32 almost surely.
__global__ void rd_detect_kernel(const long long* __restrict__ ei,
                                 int nsample, int n_nodes) {
    int i = blockIdx.x * blockDim.x + threadIdx.x;
    if (i < nsample) {
        long long v = ei[i];
        if (v < 0 || v >= (long long)n_nodes) atomicExch(&g_is64, 0);
    }
}

// mask[tgt[e]] = 1. Targets are row 1 of edge_index (2, E).
__global__ void rd_scatter_kernel(const void* __restrict__ ei,
                                  long long E, int n_nodes) {
    long long e = (long long)blockIdx.x * blockDim.x + threadIdx.x;
    if (e >= E) return;
    long long t;
    if (g_is64) t = ((const long long*)ei)[E + e];
    else        t = (long long)((const int*)ei)[E + e];
    if (t >= 0 && t < (long long)n_nodes) g_mask[t] = 1;
}

// out[n] = mask[n] * relu(x[n] @ Wv + bv)
// Block = 256 threads = 8 warps. Warp w owns rows [4w, 4w+4); lane tx owns
// output cols {tx, tx+32, tx+64}. x tile stored k-major (sXT[k][row]) so the
// 4 row-activations per k-step are ONE broadcast LDS.128.
// Per k-step: 1 bcast LDS.128 + 3 warp-wide LDS (4 crossbar cyc) vs 12 FFMA
// (6 SM-issue cyc) -> FMA-bound.
__global__ __launch_bounds__(256)
void rd_gemm_kernel(const float* __restrict__ x,
                    const float* __restrict__ Wv,
                    const float* __restrict__ bv,
                    float* __restrict__ out, int n) {
    __shared__ float sW[DIM * DIM];                     // 36864 B
    __shared__ float sB[DIM];
    __shared__ __align__(16) float sXT[DIM][ROWS_PER_BLOCK];  // 12288 B, k-major

    const int tid  = threadIdx.x;
    const int row0 = blockIdx.x * ROWS_PER_BLOCK;

    // Load Wv: 9216 floats = 2304 float4, 9 per thread.
    {
        const float4* W4 = (const float4*)Wv;
        float4* sW4 = (float4*)sW;
#pragma unroll
        for (int i = 0; i < 9; i++) sW4[tid + 256 * i] = W4[tid + 256 * i];
    }
    if (tid < DIM) sB[tid] = bv[tid];

    // Load x tile transposed: 32 rows x 24 float4-chunks = 768 vec loads,
    // 3 per thread. Lanes sharing a k-chunk store consecutive rows -> the 4
    // scalar STS per chunk are conflict-free.
    const bool full = (row0 + ROWS_PER_BLOCK <= n);
#pragma unroll
    for (int it = 0; it < 3; it++) {
        int idx = tid + 256 * it;               // 0..767
        int r  = idx / (DIM / 4);               // 0..31
        int c4 = idx % (DIM / 4);               // 0..23
        float4 v;
        if (full || row0 + r < n)
            v = *(const float4*)(x + (size_t)(row0 + r) * DIM + c4 * 4);
        else
            v = make_float4(0.f, 0.f, 0.f, 0.f);
        sXT[c4 * 4 + 0][r] = v.x;
        sXT[c4 * 4 + 1][r] = v.y;
        sXT[c4 * 4 + 2][r] = v.z;
        sXT[c4 * 4 + 3][r] = v.w;
    }
    __syncthreads();

    const int tx = tid & 31;
    const int wr = (tid >> 5) * 4;              // first of this warp's 4 rows

    float a0x = 0.f, a0y = 0.f, a0z = 0.f;      // row wr+0, cols {tx,+32,+64}
    float a1x = 0.f, a1y = 0.f, a1z = 0.f;
    float a2x = 0.f, a2y = 0.f, a2z = 0.f;
    float a3x = 0.f, a3y = 0.f, a3z = 0.f;

#pragma unroll 8
    for (int k = 0; k < DIM; k++) {
        float4 xv = *(const float4*)&sXT[k][wr];   // broadcast LDS.128
        float w0 = sW[k * DIM + tx];
        float w1 = sW[k * DIM + tx + 32];
        float w2 = sW[k * DIM + tx + 64];
        a0x = fmaf(xv.x, w0, a0x); a0y = fmaf(xv.x, w1, a0y); a0z = fmaf(xv.x, w2, a0z);
        a1x = fmaf(xv.y, w0, a1x); a1y = fmaf(xv.y, w1, a1y); a1z = fmaf(xv.y, w2, a1z);
        a2x = fmaf(xv.z, w0, a2x); a2y = fmaf(xv.z, w1, a2y); a2z = fmaf(xv.z, w2, a2z);
        a3x = fmaf(xv.w, w0, a3x); a3y = fmaf(xv.w, w1, a3y); a3z = fmaf(xv.w, w2, a3z);
    }

    const float b0 = sB[tx];
    const float b1 = sB[tx + 32];
    const float b2 = sB[tx + 64];

    float accx[4] = {a0x, a1x, a2x, a3x};
    float accy[4] = {a0y, a1y, a2y, a3y};
    float accz[4] = {a0z, a1z, a2z, a3z};

#pragma unroll
    for (int i = 0; i < 4; i++) {
        int r = row0 + wr + i;
        if (r < n) {
            float m = g_mask[r] ? 1.f : 0.f;
            float* o = out + (size_t)r * DIM;
            o[tx]      = fmaxf(accx[i] + b0, 0.f) * m;
            o[tx + 32] = fmaxf(accy[i] + b1, 0.f) * m;
            o[tx + 64] = fmaxf(accz[i] + b2, 0.f) * m;
        }
    }
}

extern "C" void kernel_launch(void* const* d_in, const int* in_sizes, int n_in,
                              void* d_out, int out_size) {
    const float* x  = (const float*)d_in[0];
    // d_in[1] = p_t (unused, use_beta=False)
    const float* Wv = (const float*)d_in[2];
    const float* bv = (const float*)d_in[3];
    // d_in[4] = edge_weights (cancels: segment softmax sums to 1)
    const void*  ei = d_in[5];

    const int n = in_sizes[0] / DIM;                 // 50000
    const long long E = (long long)in_sizes[5] / 2;  // 800000

    {   // 1) zero mask + flag
        int threads = 256;
        int blocks = (n + threads - 1) / threads;
        rd_init_kernel<<<blocks, threads>>>(n);
    }
    {   // 2) detect int32 vs int64 edge_index
        int nsample = (int)((E / 2 < 8192) ? E / 2 : 8192);
        if (nsample > 0) {
            int threads = 256;
            int blocks = (nsample + threads - 1) / threads;
            rd_detect_kernel<<<blocks, threads>>>((const long long*)ei, nsample, n);
        }
    }
    {   // 3) scatter edge-target mask
        int threads = 256;
        int blocks = (int)((E + threads - 1) / threads);
        rd_scatter_kernel<<<blocks, threads>>>(ei, E, n);
    }
    {   // 4) masked GEMM + bias + relu
        int blocks = (n + ROWS_PER_BLOCK - 1) / ROWS_PER_BLOCK;
        rd_gemm_kernel<<<blocks, 256>>>(x, Wv, bv, (float*)d_out, n);
    }
}